// round 4
// baseline (speedup 1.0000x reference)
#include <cuda_runtime.h>
#include <cstdint>

// ---------------------------------------------------------------------------
// Problem constants (match reference setup)
// ---------------------------------------------------------------------------
#define BB        2
#define S_TOK     21760          // sum of level sizes
#define BS_TOK    (BB * S_TOK)   // 43520 tokens total
#define DMODEL    256
#define NH        8
#define DH        32
#define NL        4
#define NPT       4
#define DFF       1024

__device__ __constant__ int c_lvlW[NL]     = {128, 64, 32, 16};
__device__ __constant__ int c_lvlStart[NL] = {0, 16384, 20480, 21504};

// ---------------------------------------------------------------------------
// Scratch (static device globals; aliased across phases to cut footprint)
//   g_q    : q (steps 1-4)            -> src2 (steps 6-7)
//   g_value: value (steps 2-5)        -> x (steps 7-10)
//   g_acc  : acc (steps 5-6)          -> ffn (steps 9-10)
// ---------------------------------------------------------------------------
__device__ float g_q    [BS_TOK * DMODEL];
__device__ float g_value[BS_TOK * DMODEL];
__device__ float g_off  [BS_TOK * DMODEL];          // NH*NL*NP*2 = 256
__device__ float g_attn [BS_TOK * (NH * NL * NPT)]; // 128 logits/token
__device__ float g_acc  [BS_TOK * DMODEL];
__device__ float g_h    [BS_TOK * DFF];

// ---------------------------------------------------------------------------
// Elementwise add: q = src + pos
// ---------------------------------------------------------------------------
__global__ void add_kernel(const float* __restrict__ a,
                           const float* __restrict__ b,
                           float* __restrict__ o, int n4)
{
    int i = blockIdx.x * blockDim.x + threadIdx.x;
    if (i < n4) {
        float4 av = ((const float4*)a)[i];
        float4 bv = ((const float4*)b)[i];
        float4 ov;
        ov.x = av.x + bv.x; ov.y = av.y + bv.y;
        ov.z = av.z + bv.z; ov.w = av.w + bv.w;
        ((float4*)o)[i] = ov;
    }
}

// ---------------------------------------------------------------------------
// Tiled SGEMM: C[M,N] = A[M,K] @ W[K,N] + bias  (optional ReLU)
// BM=BN=128, BK=8, 256 threads, 8x8 microtile.
// Assumes M%128==0, N%128==0, K%8==0 (true for all calls here).
// ---------------------------------------------------------------------------
template<bool RELU>
__global__ void __launch_bounds__(256, 2)
gemm128(const float* __restrict__ A, const float* __restrict__ W,
        const float* __restrict__ bias, float* __restrict__ C,
        int M, int N, int K)
{
    __shared__ float As[8][128];
    __shared__ float Bs[8][128];

    const int tid = threadIdx.x;
    const int bm  = blockIdx.x * 128;
    const int bn  = blockIdx.y * 128;
    const int tx  = tid & 15;   // 0..15  (N dir)
    const int ty  = tid >> 4;   // 0..15  (M dir)

    // global load assignments
    const int arow = tid >> 1;          // 0..127
    const int acol = (tid & 1) * 4;     // 0 or 4
    const int brow = tid >> 5;          // 0..7
    const int bcol = (tid & 31) * 4;    // 0..124

    const float* Aptr = A + (size_t)(bm + arow) * K + acol;
    const float* Wptr = W + (size_t)brow * N + bn + bcol;

    float acc[8][8];
    #pragma unroll
    for (int i = 0; i < 8; i++)
        #pragma unroll
        for (int j = 0; j < 8; j++) acc[i][j] = 0.f;

    for (int k0 = 0; k0 < K; k0 += 8) {
        float4 av = *(const float4*)Aptr;
        float4 bv = *(const float4*)Wptr;
        As[acol + 0][arow] = av.x;
        As[acol + 1][arow] = av.y;
        As[acol + 2][arow] = av.z;
        As[acol + 3][arow] = av.w;
        *(float4*)&Bs[brow][bcol] = bv;
        __syncthreads();

        #pragma unroll
        for (int k = 0; k < 8; k++) {
            float a[8], b[8];
            *(float4*)(a)     = *(const float4*)&As[k][ty * 8];
            *(float4*)(a + 4) = *(const float4*)&As[k][ty * 8 + 4];
            *(float4*)(b)     = *(const float4*)&Bs[k][tx * 8];
            *(float4*)(b + 4) = *(const float4*)&Bs[k][tx * 8 + 4];
            #pragma unroll
            for (int i = 0; i < 8; i++)
                #pragma unroll
                for (int j = 0; j < 8; j++)
                    acc[i][j] += a[i] * b[j];
        }
        __syncthreads();
        Aptr += 8;
        Wptr += (size_t)8 * N;
    }

    // epilogue: bias (+ReLU), vectorized store
    #pragma unroll
    for (int i = 0; i < 8; i++) {
        const size_t row = (size_t)(bm + ty * 8 + i);
        #pragma unroll
        for (int j = 0; j < 8; j += 4) {
            const int col = bn + tx * 8 + j;
            float4 v;
            v.x = acc[i][j + 0] + bias[col + 0];
            v.y = acc[i][j + 1] + bias[col + 1];
            v.z = acc[i][j + 2] + bias[col + 2];
            v.w = acc[i][j + 3] + bias[col + 3];
            if (RELU) {
                v.x = fmaxf(v.x, 0.f); v.y = fmaxf(v.y, 0.f);
                v.z = fmaxf(v.z, 0.f); v.w = fmaxf(v.w, 0.f);
            }
            *(float4*)&C[row * N + col] = v;
        }
    }
}

// ---------------------------------------------------------------------------
// Deformable sampling: one warp per (token, head), lane = channel (DH=32).
// Reads g_value, g_off, g_attn + reference_points; writes g_acc.
// ---------------------------------------------------------------------------
__global__ void __launch_bounds__(256)
sample_kernel(const float* __restrict__ refpts)
{
    const int warp = (blockIdx.x * blockDim.x + threadIdx.x) >> 5;
    const int lane = threadIdx.x & 31;
    if (warp >= BS_TOK * NH) return;
    const int h = warp & (NH - 1);
    const int t = warp >> 3;                 // global token (b*S + q)
    const int b = t / S_TOK;
    const int base = b * S_TOK;              // value row base for this batch

    // softmax over 16 logits (redundant per lane; L1-broadcast loads)
    const float* lg = g_attn + (size_t)t * 128 + h * 16;
    float w[16];
    float mx = -1e30f;
    #pragma unroll
    for (int i = 0; i < 16; i++) { w[i] = lg[i]; mx = fmaxf(mx, w[i]); }
    float ssum = 0.f;
    #pragma unroll
    for (int i = 0; i < 16; i++) { w[i] = __expf(w[i] - mx); ssum += w[i]; }
    const float inv = 1.f / ssum;

    const float* offp = g_off + (size_t)t * 256 + h * 32; // (NL,NP,2)
    const float* rp   = refpts + (size_t)t * NL * 2;      // (NL,2)

    float acc = 0.f;
    #pragma unroll
    for (int l = 0; l < NL; l++) {
        const int W = c_lvlW[l];
        const int H = W;
        const int lstart = c_lvlStart[l];
        const float rx = rp[l * 2 + 0];
        const float ry = rp[l * 2 + 1];
        #pragma unroll
        for (int p = 0; p < NPT; p++) {
            const float ox = offp[l * 8 + p * 2 + 0];
            const float oy = offp[l * 8 + p * 2 + 1];
            // mirror reference rounding: loc = ref + off/norm; x = loc*W - 0.5
            const float locx = rx + ox / (float)W;
            const float locy = ry + oy / (float)H;
            const float x = locx * (float)W - 0.5f;
            const float y = locy * (float)H - 0.5f;
            const float x0f = floorf(x), y0f = floorf(y);
            const float wx = x - x0f, wy = y - y0f;
            const int x0 = (int)x0f, y0 = (int)y0f;
            const float aw = w[l * 4 + p] * inv;

            float v00 = 0.f, v01 = 0.f, v10 = 0.f, v11 = 0.f;
            if (x0 >= 0 && x0 < W && y0 >= 0 && y0 < H)
                v00 = g_value[(size_t)(base + lstart + y0 * W + x0) * 256 + h * 32 + lane];
            if (x0 + 1 >= 0 && x0 + 1 < W && y0 >= 0 && y0 < H)
                v01 = g_value[(size_t)(base + lstart + y0 * W + x0 + 1) * 256 + h * 32 + lane];
            if (x0 >= 0 && x0 < W && y0 + 1 >= 0 && y0 + 1 < H)
                v10 = g_value[(size_t)(base + lstart + (y0 + 1) * W + x0) * 256 + h * 32 + lane];
            if (x0 + 1 >= 0 && x0 + 1 < W && y0 + 1 >= 0 && y0 + 1 < H)
                v11 = g_value[(size_t)(base + lstart + (y0 + 1) * W + x0 + 1) * 256 + h * 32 + lane];

            const float s = v00 * ((1.f - wx) * (1.f - wy))
                          + v01 * (wx * (1.f - wy))
                          + v10 * ((1.f - wx) * wy)
                          + v11 * (wx * wy);
            acc += aw * s;
        }
    }
    g_acc[(size_t)t * 256 + h * 32 + lane] = acc;
}

// ---------------------------------------------------------------------------
// out = LayerNorm(a + b) * g + beta, over D=256 per token. 1 block / token.
// ---------------------------------------------------------------------------
__global__ void __launch_bounds__(256)
add_ln_kernel(const float* __restrict__ a, const float* __restrict__ b,
              const float* __restrict__ g, const float* __restrict__ be,
              float* __restrict__ out)
{
    const int t = blockIdx.x;
    const int i = threadIdx.x;
    const size_t idx = (size_t)t * DMODEL + i;
    const float v = a[idx] + b[idx];

    float s = v, s2 = v * v;
    #pragma unroll
    for (int o = 16; o > 0; o >>= 1) {
        s  += __shfl_xor_sync(0xffffffffu, s,  o);
        s2 += __shfl_xor_sync(0xffffffffu, s2, o);
    }
    __shared__ float sh[8], sh2[8];
    const int wid = i >> 5, lane = i & 31;
    if (lane == 0) { sh[wid] = s; sh2[wid] = s2; }
    __syncthreads();
    float ts = 0.f, ts2 = 0.f;
    #pragma unroll
    for (int k = 0; k < 8; k++) { ts += sh[k]; ts2 += sh2[k]; }

    const float mean = ts * (1.f / DMODEL);
    const float var  = ts2 * (1.f / DMODEL) - mean * mean;
    const float rstd = rsqrtf(var + 1e-5f);
    out[idx] = (v - mean) * rstd * g[i] + be[i];
}

// ---------------------------------------------------------------------------
// Launch
// ---------------------------------------------------------------------------
extern "C" void kernel_launch(void* const* d_in, const int* in_sizes, int n_in,
                              void* d_out, int out_size)
{
    const float* src    = (const float*)d_in[0];
    const float* pos    = (const float*)d_in[1];
    const float* refpts = (const float*)d_in[2];
    // d_in[3] spatial_shapes, d_in[4] level_start_index: compile-time constants
    const float* W_off  = (const float*)d_in[5];
    const float* b_off  = (const float*)d_in[6];
    const float* W_attn = (const float*)d_in[7];
    const float* b_attn = (const float*)d_in[8];
    const float* W_val  = (const float*)d_in[9];
    const float* b_val  = (const float*)d_in[10];
    const float* W_out  = (const float*)d_in[11];
    const float* b_out  = (const float*)d_in[12];
    const float* W_ffn1 = (const float*)d_in[13];
    const float* b_ffn1 = (const float*)d_in[14];
    const float* W_ffn2 = (const float*)d_in[15];
    const float* b_ffn2 = (const float*)d_in[16];
    const float* ln1_g  = (const float*)d_in[17];
    const float* ln1_b  = (const float*)d_in[18];
    const float* ln2_g  = (const float*)d_in[19];
    const float* ln2_b  = (const float*)d_in[20];
    float* out = (float*)d_out;

    float *q, *value, *off, *attn, *acc, *h;
    cudaGetSymbolAddress((void**)&q,     g_q);
    cudaGetSymbolAddress((void**)&value, g_value);
    cudaGetSymbolAddress((void**)&off,   g_off);
    cudaGetSymbolAddress((void**)&attn,  g_attn);
    cudaGetSymbolAddress((void**)&acc,   g_acc);
    cudaGetSymbolAddress((void**)&h,     g_h);

    // buffer aliasing (lifetimes don't overlap):
    float* src2 = q;      // q dead after step 4; src2 live steps 6-7
    float* x    = value;  // value dead after step 5; x live steps 7-10
    float* ffn  = acc;    // acc dead after step 6; ffn live steps 9-10

    const int MB = BS_TOK / 128;   // 340 row-tiles

    // 1) q = src + pos
    {
        int n4 = BS_TOK * DMODEL / 4;
        add_kernel<<<(n4 + 255) / 256, 256>>>(src, pos, q, n4);
    }
    // 2) value = src @ W_val + b_val
    gemm128<false><<<dim3(MB, DMODEL / 128), 256>>>(src, W_val, b_val, value,
                                                    BS_TOK, DMODEL, DMODEL);
    // 3) off = q @ W_off + b_off
    gemm128<false><<<dim3(MB, 256 / 128), 256>>>(q, W_off, b_off, off,
                                                 BS_TOK, 256, DMODEL);
    // 4) attn logits = q @ W_attn + b_attn
    gemm128<false><<<dim3(MB, 1), 256>>>(q, W_attn, b_attn, attn,
                                         BS_TOK, 128, DMODEL);
    // 5) deformable sampling -> acc
    {
        int warps = BS_TOK * NH;                  // 348160
        int blocks = warps / 8;                   // 256 thr = 8 warps
        sample_kernel<<<blocks, 256>>>(refpts);
    }
    // 6) src2 = acc @ W_out + b_out   (src2 aliases q — q no longer needed)
    gemm128<false><<<dim3(MB, DMODEL / 128), 256>>>(acc, W_out, b_out, src2,
                                                    BS_TOK, DMODEL, DMODEL);
    // 7) x = LN(src + src2)           (x aliases value — value no longer needed)
    add_ln_kernel<<<BS_TOK, 256>>>(src, src2, ln1_g, ln1_b, x);
    // 8) h = relu(x @ W_ffn1 + b_ffn1)
    gemm128<true><<<dim3(MB, DFF / 128), 256>>>(x, W_ffn1, b_ffn1, h,
                                                BS_TOK, DFF, DMODEL);
    // 9) ffn = h @ W_ffn2 + b_ffn2    (ffn aliases acc — acc no longer needed)
    gemm128<false><<<dim3(MB, DMODEL / 128), 256>>>(h, W_ffn2, b_ffn2, ffn,
                                                    BS_TOK, DMODEL, DFF);
    // 10) out = LN(x + ffn)
    add_ln_kernel<<<BS_TOK, 256>>>(x, ffn, ln2_g, ln2_b, out);
}

// round 12
// speedup vs baseline: 1.7043x; 1.7043x over previous
#include <cuda_runtime.h>
#include <cstdint>

// ---------------------------------------------------------------------------
// Problem constants (match reference setup)
// ---------------------------------------------------------------------------
#define BB        2
#define S_TOK     21760          // sum of level sizes
#define BS_TOK    (BB * S_TOK)   // 43520 tokens total
#define DMODEL    256
#define NH        8
#define DH        32
#define NL        4
#define NPT       4
#define DFF       1024

__device__ __constant__ int c_lvlW[NL]     = {128, 64, 32, 16};
__device__ __constant__ int c_lvlStart[NL] = {0, 16384, 20480, 21504};

// ---------------------------------------------------------------------------
// Scratch (static device globals; aliased across phases to cut footprint)
// ---------------------------------------------------------------------------
__device__ float g_q    [BS_TOK * DMODEL];
__device__ float g_value[BS_TOK * DMODEL];
__device__ float g_off  [BS_TOK * DMODEL];          // NH*NL*NP*2 = 256
__device__ float g_attn [BS_TOK * (NH * NL * NPT)]; // 128 logits/token
__device__ float g_acc  [BS_TOK * DMODEL];
__device__ float g_h    [BS_TOK * DFF];

// ---------------------------------------------------------------------------
// Elementwise add: q = src + pos
// ---------------------------------------------------------------------------
__global__ void add_kernel(const float* __restrict__ a,
                           const float* __restrict__ b,
                           float* __restrict__ o, int n4)
{
    int i = blockIdx.x * blockDim.x + threadIdx.x;
    if (i < n4) {
        float4 av = ((const float4*)a)[i];
        float4 bv = ((const float4*)b)[i];
        float4 ov;
        ov.x = av.x + bv.x; ov.y = av.y + bv.y;
        ov.z = av.z + bv.z; ov.w = av.w + bv.w;
        ((float4*)o)[i] = ov;
    }
}

// ---------------------------------------------------------------------------
// tf32 helpers
// ---------------------------------------------------------------------------
__device__ __forceinline__ uint32_t f2tf32(float f) {
    uint32_t r;
    asm("cvt.rna.tf32.f32 %0, %1;" : "=r"(r) : "f"(f));
    return r;
}

__device__ __forceinline__ void mma_tf32(float c[4],
                                         uint32_t a0, uint32_t a1,
                                         uint32_t a2, uint32_t a3,
                                         uint32_t b0, uint32_t b1)
{
    asm volatile(
        "mma.sync.aligned.m16n8k8.row.col.f32.tf32.tf32.f32 "
        "{%0,%1,%2,%3}, {%4,%5,%6,%7}, {%8,%9}, {%0,%1,%2,%3};"
        : "+f"(c[0]), "+f"(c[1]), "+f"(c[2]), "+f"(c[3])
        : "r"(a0), "r"(a1), "r"(a2), "r"(a3), "r"(b0), "r"(b1));
}

// ---------------------------------------------------------------------------
// tf32 tensor-core GEMM: C[M,N] = A[M,K] @ W[K,N] + bias (optional ReLU)
// BM=BN=128, BK=16, 256 threads = 8 warps (2 m x 4 n), warp tile 64x32.
// mma m16n8k8: per warp 4 m-frags x 4 n-frags.
// Requires M%128==0, N%128==0, K%16==0 (true for all calls here).
// Smem k-major [16][136]: stride 136 % 32 == 8 -> fragment LDS conflict-free.
// ---------------------------------------------------------------------------
#define SPAD 136

template<bool RELU>
__global__ void __launch_bounds__(256)
gemm_tf32(const float* __restrict__ A, const float* __restrict__ W,
          const float* __restrict__ bias, float* __restrict__ C,
          int M, int N, int K)
{
    __shared__ float As[16][SPAD];
    __shared__ float Bs[16][SPAD];

    const int tid  = threadIdx.x;
    const int lane = tid & 31;
    const int warp = tid >> 5;
    const int wm   = warp & 1;     // 0..1 (m dir, 64 rows each)
    const int wn   = warp >> 1;    // 0..3 (n dir, 32 cols each)
    const int bm   = blockIdx.x * 128;
    const int bn   = blockIdx.y * 128;
    const int gid  = lane >> 2;    // 0..7
    const int tig  = lane & 3;     // 0..3

    float c[4][4][4];
    #pragma unroll
    for (int mf = 0; mf < 4; mf++)
        #pragma unroll
        for (int nf = 0; nf < 4; nf++)
            #pragma unroll
            for (int i = 0; i < 4; i++) c[mf][nf][i] = 0.f;

    for (int k0 = 0; k0 < K; k0 += 16) {
        // ---- load A tile (128 x 16), transpose to k-major smem ----
        #pragma unroll
        for (int u = 0; u < 2; u++) {
            int idx = tid + u * 256;           // 0..511
            int m  = idx >> 2;                 // 0..127
            int kk = (idx & 3) * 4;            // 0,4,8,12
            float4 v = *(const float4*)(A + (size_t)(bm + m) * K + k0 + kk);
            As[kk + 0][m] = __uint_as_float(f2tf32(v.x));
            As[kk + 1][m] = __uint_as_float(f2tf32(v.y));
            As[kk + 2][m] = __uint_as_float(f2tf32(v.z));
            As[kk + 3][m] = __uint_as_float(f2tf32(v.w));
        }
        // ---- load B tile (16 x 128), already k-major ----
        #pragma unroll
        for (int u = 0; u < 2; u++) {
            int idx = tid + u * 256;           // 0..511
            int kb = idx >> 5;                 // 0..15
            int nb = (idx & 31) * 4;           // 0..124
            float4 v = *(const float4*)(W + (size_t)(k0 + kb) * N + bn + nb);
            float4 t;
            t.x = __uint_as_float(f2tf32(v.x));
            t.y = __uint_as_float(f2tf32(v.y));
            t.z = __uint_as_float(f2tf32(v.z));
            t.w = __uint_as_float(f2tf32(v.w));
            *(float4*)&Bs[kb][nb] = t;
        }
        __syncthreads();

        // ---- 2 k-steps of 8 ----
        #pragma unroll
        for (int ks = 0; ks < 2; ks++) {
            const int kb = ks * 8;
            uint32_t afr[4][4], bfr[4][2];
            #pragma unroll
            for (int mf = 0; mf < 4; mf++) {
                const int mb = wm * 64 + mf * 16;
                afr[mf][0] = __float_as_uint(As[kb + tig    ][mb + gid    ]);
                afr[mf][1] = __float_as_uint(As[kb + tig    ][mb + gid + 8]);
                afr[mf][2] = __float_as_uint(As[kb + tig + 4][mb + gid    ]);
                afr[mf][3] = __float_as_uint(As[kb + tig + 4][mb + gid + 8]);
            }
            #pragma unroll
            for (int nf = 0; nf < 4; nf++) {
                const int nb = wn * 32 + nf * 8;
                bfr[nf][0] = __float_as_uint(Bs[kb + tig    ][nb + gid]);
                bfr[nf][1] = __float_as_uint(Bs[kb + tig + 4][nb + gid]);
            }
            #pragma unroll
            for (int mf = 0; mf < 4; mf++)
                #pragma unroll
                for (int nf = 0; nf < 4; nf++)
                    mma_tf32(c[mf][nf],
                             afr[mf][0], afr[mf][1], afr[mf][2], afr[mf][3],
                             bfr[nf][0], bfr[nf][1]);
        }
        __syncthreads();
    }

    // ---- epilogue: bias (+ReLU) ----
    #pragma unroll
    for (int mf = 0; mf < 4; mf++) {
        const int r0 = bm + wm * 64 + mf * 16 + gid;
        #pragma unroll
        for (int nf = 0; nf < 4; nf++) {
            const int col = bn + wn * 32 + nf * 8 + 2 * tig;
            const float bx = bias[col], by = bias[col + 1];
            float2 v0, v1;
            v0.x = c[mf][nf][0] + bx; v0.y = c[mf][nf][1] + by;
            v1.x = c[mf][nf][2] + bx; v1.y = c[mf][nf][3] + by;
            if (RELU) {
                v0.x = fmaxf(v0.x, 0.f); v0.y = fmaxf(v0.y, 0.f);
                v1.x = fmaxf(v1.x, 0.f); v1.y = fmaxf(v1.y, 0.f);
            }
            *(float2*)&C[(size_t)r0       * N + col] = v0;
            *(float2*)&C[(size_t)(r0 + 8) * N + col] = v1;
        }
    }
}

// ---------------------------------------------------------------------------
// Deformable sampling: one warp per (token, head), lane = channel (DH=32).
// ---------------------------------------------------------------------------
__global__ void __launch_bounds__(256)
sample_kernel(const float* __restrict__ refpts)
{
    const int warp = (blockIdx.x * blockDim.x + threadIdx.x) >> 5;
    const int lane = threadIdx.x & 31;
    if (warp >= BS_TOK * NH) return;
    const int h = warp & (NH - 1);
    const int t = warp >> 3;                 // global token (b*S + q)
    const int b = t / S_TOK;
    const int base = b * S_TOK;              // value row base for this batch

    // softmax over 16 logits (redundant per lane; L1-broadcast loads)
    const float* lg = g_attn + (size_t)t * 128 + h * 16;
    float w[16];
    float mx = -1e30f;
    #pragma unroll
    for (int i = 0; i < 16; i++) { w[i] = lg[i]; mx = fmaxf(mx, w[i]); }
    float ssum = 0.f;
    #pragma unroll
    for (int i = 0; i < 16; i++) { w[i] = __expf(w[i] - mx); ssum += w[i]; }
    const float inv = 1.f / ssum;

    const float* offp = g_off + (size_t)t * 256 + h * 32; // (NL,NP,2)
    const float* rp   = refpts + (size_t)t * NL * 2;      // (NL,2)

    float acc = 0.f;
    #pragma unroll
    for (int l = 0; l < NL; l++) {
        const int W = c_lvlW[l];
        const int H = W;
        const int lstart = c_lvlStart[l];
        const float rx = rp[l * 2 + 0];
        const float ry = rp[l * 2 + 1];
        #pragma unroll
        for (int p = 0; p < NPT; p++) {
            const float ox = offp[l * 8 + p * 2 + 0];
            const float oy = offp[l * 8 + p * 2 + 1];
            // mirror reference rounding: loc = ref + off/norm; x = loc*W - 0.5
            const float locx = rx + ox / (float)W;
            const float locy = ry + oy / (float)H;
            const float x = locx * (float)W - 0.5f;
            const float y = locy * (float)H - 0.5f;
            const float x0f = floorf(x), y0f = floorf(y);
            const float wx = x - x0f, wy = y - y0f;
            const int x0 = (int)x0f, y0 = (int)y0f;
            const float aw = w[l * 4 + p] * inv;

            float v00 = 0.f, v01 = 0.f, v10 = 0.f, v11 = 0.f;
            if (x0 >= 0 && x0 < W && y0 >= 0 && y0 < H)
                v00 = g_value[(size_t)(base + lstart + y0 * W + x0) * 256 + h * 32 + lane];
            if (x0 + 1 >= 0 && x0 + 1 < W && y0 >= 0 && y0 < H)
                v01 = g_value[(size_t)(base + lstart + y0 * W + x0 + 1) * 256 + h * 32 + lane];
            if (x0 >= 0 && x0 < W && y0 + 1 >= 0 && y0 + 1 < H)
                v10 = g_value[(size_t)(base + lstart + (y0 + 1) * W + x0) * 256 + h * 32 + lane];
            if (x0 + 1 >= 0 && x0 + 1 < W && y0 + 1 >= 0 && y0 + 1 < H)
                v11 = g_value[(size_t)(base + lstart + (y0 + 1) * W + x0 + 1) * 256 + h * 32 + lane];

            const float s = v00 * ((1.f - wx) * (1.f - wy))
                          + v01 * (wx * (1.f - wy))
                          + v10 * ((1.f - wx) * wy)
                          + v11 * (wx * wy);
            acc += aw * s;
        }
    }
    g_acc[(size_t)t * 256 + h * 32 + lane] = acc;
}

// ---------------------------------------------------------------------------
// out = LayerNorm(a + b) * g + beta, over D=256 per token. 1 block / token.
// ---------------------------------------------------------------------------
__global__ void __launch_bounds__(256)
add_ln_kernel(const float* __restrict__ a, const float* __restrict__ b,
              const float* __restrict__ g, const float* __restrict__ be,
              float* __restrict__ out)
{
    const int t = blockIdx.x;
    const int i = threadIdx.x;
    const size_t idx = (size_t)t * DMODEL + i;
    const float v = a[idx] + b[idx];

    float s = v, s2 = v * v;
    #pragma unroll
    for (int o = 16; o > 0; o >>= 1) {
        s  += __shfl_xor_sync(0xffffffffu, s,  o);
        s2 += __shfl_xor_sync(0xffffffffu, s2, o);
    }
    __shared__ float sh[8], sh2[8];
    const int wid = i >> 5, lane = i & 31;
    if (lane == 0) { sh[wid] = s; sh2[wid] = s2; }
    __syncthreads();
    float ts = 0.f, ts2 = 0.f;
    #pragma unroll
    for (int k = 0; k < 8; k++) { ts += sh[k]; ts2 += sh2[k]; }

    const float mean = ts * (1.f / DMODEL);
    const float var  = ts2 * (1.f / DMODEL) - mean * mean;
    const float rstd = rsqrtf(var + 1e-5f);
    out[idx] = (v - mean) * rstd * g[i] + be[i];
}

// ---------------------------------------------------------------------------
// Launch
// ---------------------------------------------------------------------------
extern "C" void kernel_launch(void* const* d_in, const int* in_sizes, int n_in,
                              void* d_out, int out_size)
{
    const float* src    = (const float*)d_in[0];
    const float* pos    = (const float*)d_in[1];
    const float* refpts = (const float*)d_in[2];
    // d_in[3] spatial_shapes, d_in[4] level_start_index: compile-time constants
    const float* W_off  = (const float*)d_in[5];
    const float* b_off  = (const float*)d_in[6];
    const float* W_attn = (const float*)d_in[7];
    const float* b_attn = (const float*)d_in[8];
    const float* W_val  = (const float*)d_in[9];
    const float* b_val  = (const float*)d_in[10];
    const float* W_out  = (const float*)d_in[11];
    const float* b_out  = (const float*)d_in[12];
    const float* W_ffn1 = (const float*)d_in[13];
    const float* b_ffn1 = (const float*)d_in[14];
    const float* W_ffn2 = (const float*)d_in[15];
    const float* b_ffn2 = (const float*)d_in[16];
    const float* ln1_g  = (const float*)d_in[17];
    const float* ln1_b  = (const float*)d_in[18];
    const float* ln2_g  = (const float*)d_in[19];
    const float* ln2_b  = (const float*)d_in[20];
    float* out = (float*)d_out;

    float *q, *value, *off, *attn, *acc, *h;
    cudaGetSymbolAddress((void**)&q,     g_q);
    cudaGetSymbolAddress((void**)&value, g_value);
    cudaGetSymbolAddress((void**)&off,   g_off);
    cudaGetSymbolAddress((void**)&attn,  g_attn);
    cudaGetSymbolAddress((void**)&acc,   g_acc);
    cudaGetSymbolAddress((void**)&h,     g_h);

    // buffer aliasing (lifetimes don't overlap):
    float* src2 = q;      // q dead after step 4; src2 live steps 6-7
    float* x    = value;  // value dead after step 5; x live steps 7-10
    float* ffn  = acc;    // acc dead after step 6; ffn live steps 9-10

    const int MB = BS_TOK / 128;   // 340 row-tiles

    // 1) q = src + pos
    {
        int n4 = BS_TOK * DMODEL / 4;
        add_kernel<<<(n4 + 255) / 256, 256>>>(src, pos, q, n4);
    }
    // 2) value = src @ W_val + b_val
    gemm_tf32<false><<<dim3(MB, DMODEL / 128), 256>>>(src, W_val, b_val, value,
                                                      BS_TOK, DMODEL, DMODEL);
    // 3) off = q @ W_off + b_off
    gemm_tf32<false><<<dim3(MB, 256 / 128), 256>>>(q, W_off, b_off, off,
                                                   BS_TOK, 256, DMODEL);
    // 4) attn logits = q @ W_attn + b_attn
    gemm_tf32<false><<<dim3(MB, 1), 256>>>(q, W_attn, b_attn, attn,
                                           BS_TOK, 128, DMODEL);
    // 5) deformable sampling -> acc
    {
        int warps = BS_TOK * NH;                  // 348160
        int blocks = warps / 8;                   // 256 thr = 8 warps
        sample_kernel<<<blocks, 256>>>(refpts);
    }
    // 6) src2 = acc @ W_out + b_out   (src2 aliases q)
    gemm_tf32<false><<<dim3(MB, DMODEL / 128), 256>>>(acc, W_out, b_out, src2,
                                                      BS_TOK, DMODEL, DMODEL);
    // 7) x = LN(src + src2)           (x aliases value)
    add_ln_kernel<<<BS_TOK, 256>>>(src, src2, ln1_g, ln1_b, x);
    // 8) h = relu(x @ W_ffn1 + b_ffn1)
    gemm_tf32<true><<<dim3(MB, DFF / 128), 256>>>(x, W_ffn1, b_ffn1, h,
                                                  BS_TOK, DFF, DMODEL);
    // 9) ffn = h @ W_ffn2 + b_ffn2    (ffn aliases acc)
    gemm_tf32<false><<<dim3(MB, DMODEL / 128), 256>>>(h, W_ffn2, b_ffn2, ffn,
                                                      BS_TOK, DMODEL, DFF);
    // 10) out = LN(x + ffn)
    add_ln_kernel<<<BS_TOK, 256>>>(x, ffn, ln2_g, ln2_b, out);
}

// round 13
// speedup vs baseline: 1.9363x; 1.1361x over previous
#include <cuda_runtime.h>
#include <cstdint>

// ---------------------------------------------------------------------------
// Problem constants (match reference setup)
// ---------------------------------------------------------------------------
#define BB        2
#define S_TOK     21760          // sum of level sizes
#define BS_TOK    (BB * S_TOK)   // 43520 tokens total
#define DMODEL    256
#define NH        8
#define DH        32
#define NL        4
#define NPT       4
#define DFF       1024

__device__ __constant__ int c_lvlW[NL]     = {128, 64, 32, 16};
__device__ __constant__ int c_lvlStart[NL] = {0, 16384, 20480, 21504};

// ---------------------------------------------------------------------------
// Scratch (static device globals; aliased across phases to cut footprint)
// ---------------------------------------------------------------------------
__device__ float g_q    [BS_TOK * DMODEL];
__device__ float g_value[BS_TOK * DMODEL];
__device__ float g_off  [BS_TOK * DMODEL];          // NH*NL*NP*2 = 256
__device__ float g_attn [BS_TOK * (NH * NL * NPT)]; // 128 logits/token
__device__ float g_acc  [BS_TOK * DMODEL];
__device__ float g_h    [BS_TOK * DFF];

// ---------------------------------------------------------------------------
// Elementwise add: q = src + pos
// ---------------------------------------------------------------------------
__global__ void add_kernel(const float* __restrict__ a,
                           const float* __restrict__ b,
                           float* __restrict__ o, int n4)
{
    int i = blockIdx.x * blockDim.x + threadIdx.x;
    if (i < n4) {
        float4 av = ((const float4*)a)[i];
        float4 bv = ((const float4*)b)[i];
        float4 ov;
        ov.x = av.x + bv.x; ov.y = av.y + bv.y;
        ov.z = av.z + bv.z; ov.w = av.w + bv.w;
        ((float4*)o)[i] = ov;
    }
}

// ---------------------------------------------------------------------------
// mma + cp.async helpers
// ---------------------------------------------------------------------------
__device__ __forceinline__ void mma_tf32(float c[4],
                                         uint32_t a0, uint32_t a1,
                                         uint32_t a2, uint32_t a3,
                                         uint32_t b0, uint32_t b1)
{
    asm volatile(
        "mma.sync.aligned.m16n8k8.row.col.f32.tf32.tf32.f32 "
        "{%0,%1,%2,%3}, {%4,%5,%6,%7}, {%8,%9}, {%0,%1,%2,%3};"
        : "+f"(c[0]), "+f"(c[1]), "+f"(c[2]), "+f"(c[3])
        : "r"(a0), "r"(a1), "r"(a2), "r"(a3), "r"(b0), "r"(b1));
}

__device__ __forceinline__ void cp_async16(uint32_t smem_addr, const void* gptr) {
    asm volatile("cp.async.cg.shared.global [%0], [%1], 16;"
                 :: "r"(smem_addr), "l"(gptr));
}
#define CP_COMMIT() asm volatile("cp.async.commit_group;" ::: "memory")
#define CP_WAIT1()  asm volatile("cp.async.wait_group 1;" ::: "memory")

// ---------------------------------------------------------------------------
// tf32 tensor-core GEMM with cp.async double buffering.
// C[M,N] = A[M,K] @ W[K,N] + bias (optional ReLU)
// BM=BN=128, BK=16, 256 threads = 8 warps (2 m x 4 n), warp tile 64x32.
// A smem: m-major [128][20]  (stride 20: 20*gid mod 32 covers all banks -> CF)
// B smem: k-major [16][136]  (stride 136 = 8 mod 32 -> CF)
// Raw fp32 bits fed to tf32 mma (HW ignores low 13 mantissa bits).
// Requires M%128==0, N%128==0, K%16==0.
// ---------------------------------------------------------------------------
#define ASTRIDE 20
#define BSTRIDE 136

template<bool RELU>
__global__ void __launch_bounds__(256)
gemm_tf32(const float* __restrict__ A, const float* __restrict__ W,
          const float* __restrict__ bias, float* __restrict__ C,
          int M, int N, int K)
{
    __shared__ float As[2][128][ASTRIDE];
    __shared__ float Bs[2][16][BSTRIDE];

    const int tid  = threadIdx.x;
    const int lane = tid & 31;
    const int warp = tid >> 5;
    const int wm   = warp & 1;     // 0..1 (m dir, 64 rows each)
    const int wn   = warp >> 1;    // 0..3 (n dir, 32 cols each)
    const int bm   = blockIdx.x * 128;
    const int bn   = blockIdx.y * 128;
    const int gid  = lane >> 2;    // 0..7
    const int tig  = lane & 3;     // 0..3

    // per-thread 16B-chunk coordinates (2 chunks each for A and B per tile)
    const int ar0 = tid >> 2;            // A rows: tid>>2 and +64
    const int ac0 = (tid & 3) * 4;       // A col offset: 0,4,8,12
    const int bk0 = tid >> 5;            // B k-rows: tid>>5 and +8
    const int bn0 = (tid & 31) * 4;      // B col offset: 0..124

    float c[4][4][4];
    #pragma unroll
    for (int mf = 0; mf < 4; mf++)
        #pragma unroll
        for (int nf = 0; nf < 4; nf++)
            #pragma unroll
            for (int i = 0; i < 4; i++) c[mf][nf][i] = 0.f;

    const int KT = K >> 4;   // # of 16-wide K tiles

    auto issue_tile = [&](int kt, int buf) {
        const int k0 = kt << 4;
        cp_async16((uint32_t)__cvta_generic_to_shared(&As[buf][ar0][ac0]),
                   A + (size_t)(bm + ar0) * K + k0 + ac0);
        cp_async16((uint32_t)__cvta_generic_to_shared(&As[buf][ar0 + 64][ac0]),
                   A + (size_t)(bm + ar0 + 64) * K + k0 + ac0);
        cp_async16((uint32_t)__cvta_generic_to_shared(&Bs[buf][bk0][bn0]),
                   W + (size_t)(k0 + bk0) * N + bn + bn0);
        cp_async16((uint32_t)__cvta_generic_to_shared(&Bs[buf][bk0 + 8][bn0]),
                   W + (size_t)(k0 + bk0 + 8) * N + bn + bn0);
    };

    issue_tile(0, 0);
    CP_COMMIT();

    for (int kt = 0; kt < KT; kt++) {
        if (kt + 1 < KT) issue_tile(kt + 1, (kt + 1) & 1);
        CP_COMMIT();                 // one group per iteration (may be empty)
        CP_WAIT1();                  // tile kt resident
        __syncthreads();

        const int buf = kt & 1;
        #pragma unroll
        for (int ks = 0; ks < 2; ks++) {
            const int kb = ks * 8;
            uint32_t afr[4][4], bfr[4][2];
            #pragma unroll
            for (int mf = 0; mf < 4; mf++) {
                const int mb = wm * 64 + mf * 16;
                afr[mf][0] = __float_as_uint(As[buf][mb + gid    ][kb + tig    ]);
                afr[mf][1] = __float_as_uint(As[buf][mb + gid + 8][kb + tig    ]);
                afr[mf][2] = __float_as_uint(As[buf][mb + gid    ][kb + tig + 4]);
                afr[mf][3] = __float_as_uint(As[buf][mb + gid + 8][kb + tig + 4]);
            }
            #pragma unroll
            for (int nf = 0; nf < 4; nf++) {
                const int nb = wn * 32 + nf * 8;
                bfr[nf][0] = __float_as_uint(Bs[buf][kb + tig    ][nb + gid]);
                bfr[nf][1] = __float_as_uint(Bs[buf][kb + tig + 4][nb + gid]);
            }
            #pragma unroll
            for (int mf = 0; mf < 4; mf++)
                #pragma unroll
                for (int nf = 0; nf < 4; nf++)
                    mma_tf32(c[mf][nf],
                             afr[mf][0], afr[mf][1], afr[mf][2], afr[mf][3],
                             bfr[nf][0], bfr[nf][1]);
        }
        __syncthreads();             // done reading buf before it is refilled
    }

    // ---- epilogue: bias (+ReLU) ----
    #pragma unroll
    for (int mf = 0; mf < 4; mf++) {
        const int r0 = bm + wm * 64 + mf * 16 + gid;
        #pragma unroll
        for (int nf = 0; nf < 4; nf++) {
            const int col = bn + wn * 32 + nf * 8 + 2 * tig;
            const float bx = bias[col], by = bias[col + 1];
            float2 v0, v1;
            v0.x = c[mf][nf][0] + bx; v0.y = c[mf][nf][1] + by;
            v1.x = c[mf][nf][2] + bx; v1.y = c[mf][nf][3] + by;
            if (RELU) {
                v0.x = fmaxf(v0.x, 0.f); v0.y = fmaxf(v0.y, 0.f);
                v1.x = fmaxf(v1.x, 0.f); v1.y = fmaxf(v1.y, 0.f);
            }
            *(float2*)&C[(size_t)r0       * N + col] = v0;
            *(float2*)&C[(size_t)(r0 + 8) * N + col] = v1;
        }
    }
}

// ---------------------------------------------------------------------------
// Deformable sampling: one warp per (token, head), lane = channel (DH=32).
// ---------------------------------------------------------------------------
__global__ void __launch_bounds__(256)
sample_kernel(const float* __restrict__ refpts)
{
    const int warp = (blockIdx.x * blockDim.x + threadIdx.x) >> 5;
    const int lane = threadIdx.x & 31;
    if (warp >= BS_TOK * NH) return;
    const int h = warp & (NH - 1);
    const int t = warp >> 3;                 // global token (b*S + q)
    const int b = t / S_TOK;
    const int base = b * S_TOK;              // value row base for this batch

    // softmax over 16 logits (redundant per lane; L1-broadcast loads)
    const float* lg = g_attn + (size_t)t * 128 + h * 16;
    float w[16];
    float mx = -1e30f;
    #pragma unroll
    for (int i = 0; i < 16; i++) { w[i] = lg[i]; mx = fmaxf(mx, w[i]); }
    float ssum = 0.f;
    #pragma unroll
    for (int i = 0; i < 16; i++) { w[i] = __expf(w[i] - mx); ssum += w[i]; }
    const float inv = 1.f / ssum;

    const float* offp = g_off + (size_t)t * 256 + h * 32; // (NL,NP,2)
    const float* rp   = refpts + (size_t)t * NL * 2;      // (NL,2)

    float acc = 0.f;
    #pragma unroll
    for (int l = 0; l < NL; l++) {
        const int W = c_lvlW[l];
        const int H = W;
        const int lstart = c_lvlStart[l];
        const float rx = rp[l * 2 + 0];
        const float ry = rp[l * 2 + 1];
        #pragma unroll
        for (int p = 0; p < NPT; p++) {
            const float ox = offp[l * 8 + p * 2 + 0];
            const float oy = offp[l * 8 + p * 2 + 1];
            // mirror reference rounding: loc = ref + off/norm; x = loc*W - 0.5
            const float locx = rx + ox / (float)W;
            const float locy = ry + oy / (float)H;
            const float x = locx * (float)W - 0.5f;
            const float y = locy * (float)H - 0.5f;
            const float x0f = floorf(x), y0f = floorf(y);
            const float wx = x - x0f, wy = y - y0f;
            const int x0 = (int)x0f, y0 = (int)y0f;
            const float aw = w[l * 4 + p] * inv;

            float v00 = 0.f, v01 = 0.f, v10 = 0.f, v11 = 0.f;
            if (x0 >= 0 && x0 < W && y0 >= 0 && y0 < H)
                v00 = g_value[(size_t)(base + lstart + y0 * W + x0) * 256 + h * 32 + lane];
            if (x0 + 1 >= 0 && x0 + 1 < W && y0 >= 0 && y0 < H)
                v01 = g_value[(size_t)(base + lstart + y0 * W + x0 + 1) * 256 + h * 32 + lane];
            if (x0 >= 0 && x0 < W && y0 + 1 >= 0 && y0 + 1 < H)
                v10 = g_value[(size_t)(base + lstart + (y0 + 1) * W + x0) * 256 + h * 32 + lane];
            if (x0 + 1 >= 0 && x0 + 1 < W && y0 + 1 >= 0 && y0 + 1 < H)
                v11 = g_value[(size_t)(base + lstart + (y0 + 1) * W + x0 + 1) * 256 + h * 32 + lane];

            const float s = v00 * ((1.f - wx) * (1.f - wy))
                          + v01 * (wx * (1.f - wy))
                          + v10 * ((1.f - wx) * wy)
                          + v11 * (wx * wy);
            acc += aw * s;
        }
    }
    g_acc[(size_t)t * 256 + h * 32 + lane] = acc;
}

// ---------------------------------------------------------------------------
// out = LayerNorm(a + b) * g + beta, over D=256 per token. 1 block / token.
// ---------------------------------------------------------------------------
__global__ void __launch_bounds__(256)
add_ln_kernel(const float* __restrict__ a, const float* __restrict__ b,
              const float* __restrict__ g, const float* __restrict__ be,
              float* __restrict__ out)
{
    const int t = blockIdx.x;
    const int i = threadIdx.x;
    const size_t idx = (size_t)t * DMODEL + i;
    const float v = a[idx] + b[idx];

    float s = v, s2 = v * v;
    #pragma unroll
    for (int o = 16; o > 0; o >>= 1) {
        s  += __shfl_xor_sync(0xffffffffu, s,  o);
        s2 += __shfl_xor_sync(0xffffffffu, s2, o);
    }
    __shared__ float sh[8], sh2[8];
    const int wid = i >> 5, lane = i & 31;
    if (lane == 0) { sh[wid] = s; sh2[wid] = s2; }
    __syncthreads();
    float ts = 0.f, ts2 = 0.f;
    #pragma unroll
    for (int k = 0; k < 8; k++) { ts += sh[k]; ts2 += sh2[k]; }

    const float mean = ts * (1.f / DMODEL);
    const float var  = ts2 * (1.f / DMODEL) - mean * mean;
    const float rstd = rsqrtf(var + 1e-5f);
    out[idx] = (v - mean) * rstd * g[i] + be[i];
}

// ---------------------------------------------------------------------------
// Launch
// ---------------------------------------------------------------------------
extern "C" void kernel_launch(void* const* d_in, const int* in_sizes, int n_in,
                              void* d_out, int out_size)
{
    const float* src    = (const float*)d_in[0];
    const float* pos    = (const float*)d_in[1];
    const float* refpts = (const float*)d_in[2];
    // d_in[3] spatial_shapes, d_in[4] level_start_index: compile-time constants
    const float* W_off  = (const float*)d_in[5];
    const float* b_off  = (const float*)d_in[6];
    const float* W_attn = (const float*)d_in[7];
    const float* b_attn = (const float*)d_in[8];
    const float* W_val  = (const float*)d_in[9];
    const float* b_val  = (const float*)d_in[10];
    const float* W_out  = (const float*)d_in[11];
    const float* b_out  = (const float*)d_in[12];
    const float* W_ffn1 = (const float*)d_in[13];
    const float* b_ffn1 = (const float*)d_in[14];
    const float* W_ffn2 = (const float*)d_in[15];
    const float* b_ffn2 = (const float*)d_in[16];
    const float* ln1_g  = (const float*)d_in[17];
    const float* ln1_b  = (const float*)d_in[18];
    const float* ln2_g  = (const float*)d_in[19];
    const float* ln2_b  = (const float*)d_in[20];
    float* out = (float*)d_out;

    float *q, *value, *off, *attn, *acc, *h;
    cudaGetSymbolAddress((void**)&q,     g_q);
    cudaGetSymbolAddress((void**)&value, g_value);
    cudaGetSymbolAddress((void**)&off,   g_off);
    cudaGetSymbolAddress((void**)&attn,  g_attn);
    cudaGetSymbolAddress((void**)&acc,   g_acc);
    cudaGetSymbolAddress((void**)&h,     g_h);

    // buffer aliasing (lifetimes don't overlap):
    float* src2 = q;      // q dead after step 4; src2 live steps 6-7
    float* x    = value;  // value dead after step 5; x live steps 7-10
    float* ffn  = acc;    // acc dead after step 6; ffn live steps 9-10

    const int MB = BS_TOK / 128;   // 340 row-tiles

    // 1) q = src + pos
    {
        int n4 = BS_TOK * DMODEL / 4;
        add_kernel<<<(n4 + 255) / 256, 256>>>(src, pos, q, n4);
    }
    // 2) value = src @ W_val + b_val
    gemm_tf32<false><<<dim3(MB, DMODEL / 128), 256>>>(src, W_val, b_val, value,
                                                      BS_TOK, DMODEL, DMODEL);
    // 3) off = q @ W_off + b_off
    gemm_tf32<false><<<dim3(MB, 256 / 128), 256>>>(q, W_off, b_off, off,
                                                   BS_TOK, 256, DMODEL);
    // 4) attn logits = q @ W_attn + b_attn
    gemm_tf32<false><<<dim3(MB, 1), 256>>>(q, W_attn, b_attn, attn,
                                           BS_TOK, 128, DMODEL);
    // 5) deformable sampling -> acc
    {
        int warps = BS_TOK * NH;                  // 348160
        int blocks = warps / 8;                   // 256 thr = 8 warps
        sample_kernel<<<blocks, 256>>>(refpts);
    }
    // 6) src2 = acc @ W_out + b_out   (src2 aliases q)
    gemm_tf32<false><<<dim3(MB, DMODEL / 128), 256>>>(acc, W_out, b_out, src2,
                                                      BS_TOK, DMODEL, DMODEL);
    // 7) x = LN(src + src2)           (x aliases value)
    add_ln_kernel<<<BS_TOK, 256>>>(src, src2, ln1_g, ln1_b, x);
    // 8) h = relu(x @ W_ffn1 + b_ffn1)
    gemm_tf32<true><<<dim3(MB, DFF / 128), 256>>>(x, W_ffn1, b_ffn1, h,
                                                  BS_TOK, DFF, DMODEL);
    // 9) ffn = h @ W_ffn2 + b_ffn2    (ffn aliases acc)
    gemm_tf32<false><<<dim3(MB, DMODEL / 128), 256>>>(h, W_ffn2, b_ffn2, ffn,
                                                      BS_TOK, DMODEL, DFF);
    // 10) out = LN(x + ffn)
    add_ln_kernel<<<BS_TOK, 256>>>(x, ffn, ln2_g, ln2_b, out);
}

// round 16
// speedup vs baseline: 2.7116x; 1.4004x over previous
#include <cuda_runtime.h>
#include <cstdint>

// ---------------------------------------------------------------------------
// Problem constants (match reference setup)
// ---------------------------------------------------------------------------
#define BB        2
#define S_TOK     21760          // sum of level sizes
#define BS_TOK    (BB * S_TOK)   // 43520 tokens total
#define DMODEL    256
#define NH        8
#define DH        32
#define NL        4
#define NPT       4
#define DFF       1024

__device__ __constant__ int c_lvlW[NL]     = {128, 64, 32, 16};
__device__ __constant__ int c_lvlStart[NL] = {0, 16384, 20480, 21504};

// ---------------------------------------------------------------------------
// Scratch (static device globals; aliased across phases to cut footprint)
// ---------------------------------------------------------------------------
__device__ float g_q    [BS_TOK * DMODEL];
__device__ float g_value[BS_TOK * DMODEL];
__device__ float g_off  [BS_TOK * DMODEL];          // NH*NL*NP*2 = 256
__device__ float g_attn [BS_TOK * (NH * NL * NPT)]; // 128 logits/token
__device__ float g_acc  [BS_TOK * DMODEL];
__device__ float g_h    [BS_TOK * DFF];

// ---------------------------------------------------------------------------
// Elementwise add: q = src + pos
// ---------------------------------------------------------------------------
__global__ void add_kernel(const float* __restrict__ a,
                           const float* __restrict__ b,
                           float* __restrict__ o, int n4)
{
    int i = blockIdx.x * blockDim.x + threadIdx.x;
    if (i < n4) {
        float4 av = ((const float4*)a)[i];
        float4 bv = ((const float4*)b)[i];
        float4 ov;
        ov.x = av.x + bv.x; ov.y = av.y + bv.y;
        ov.z = av.z + bv.z; ov.w = av.w + bv.w;
        ((float4*)o)[i] = ov;
    }
}

// ---------------------------------------------------------------------------
// mma + cp.async helpers
// ---------------------------------------------------------------------------
__device__ __forceinline__ void mma_tf32(float c[4],
                                         uint32_t a0, uint32_t a1,
                                         uint32_t a2, uint32_t a3,
                                         uint32_t b0, uint32_t b1)
{
    asm volatile(
        "mma.sync.aligned.m16n8k8.row.col.f32.tf32.tf32.f32 "
        "{%0,%1,%2,%3}, {%4,%5,%6,%7}, {%8,%9}, {%0,%1,%2,%3};"
        : "+f"(c[0]), "+f"(c[1]), "+f"(c[2]), "+f"(c[3])
        : "r"(a0), "r"(a1), "r"(a2), "r"(a3), "r"(b0), "r"(b1));
}

__device__ __forceinline__ void cp_async16(uint32_t smem_addr, const void* gptr) {
    asm volatile("cp.async.cg.shared.global [%0], [%1], 16;"
                 :: "r"(smem_addr), "l"(gptr));
}
#define CP_COMMIT() asm volatile("cp.async.commit_group;" ::: "memory")
#define CP_WAIT1()  asm volatile("cp.async.wait_group 1;" ::: "memory")

// ---------------------------------------------------------------------------
// tf32 tensor-core GEMM with cp.async double buffering.
// C[M,N] = A[M,K] @ W[K,N] + bias (optional ReLU)
// BM=BN=128, BK=16, 256 threads = 8 warps (2 m x 4 n), warp tile 64x32.
// A smem: m-major [128][20]; B smem: k-major [16][136]. Both conflict-free.
// Raw fp32 bits fed to tf32 mma (HW ignores low 13 mantissa bits).
// ---------------------------------------------------------------------------
#define ASTRIDE 20
#define BSTRIDE 136

template<bool RELU>
__global__ void __launch_bounds__(256)
gemm_tf32(const float* __restrict__ A, const float* __restrict__ W,
          const float* __restrict__ bias, float* __restrict__ C,
          int M, int N, int K)
{
    __shared__ float As[2][128][ASTRIDE];
    __shared__ float Bs[2][16][BSTRIDE];

    const int tid  = threadIdx.x;
    const int lane = tid & 31;
    const int warp = tid >> 5;
    const int wm   = warp & 1;     // 0..1 (m dir, 64 rows each)
    const int wn   = warp >> 1;    // 0..3 (n dir, 32 cols each)
    const int bm   = blockIdx.x * 128;
    const int bn   = blockIdx.y * 128;
    const int gid  = lane >> 2;    // 0..7
    const int tig  = lane & 3;     // 0..3

    const int ar0 = tid >> 2;            // A rows: tid>>2 and +64
    const int ac0 = (tid & 3) * 4;       // A col offset: 0,4,8,12
    const int bk0 = tid >> 5;            // B k-rows: tid>>5 and +8
    const int bn0 = (tid & 31) * 4;      // B col offset: 0..124

    float c[4][4][4];
    #pragma unroll
    for (int mf = 0; mf < 4; mf++)
        #pragma unroll
        for (int nf = 0; nf < 4; nf++)
            #pragma unroll
            for (int i = 0; i < 4; i++) c[mf][nf][i] = 0.f;

    const int KT = K >> 4;

    auto issue_tile = [&](int kt, int buf) {
        const int k0 = kt << 4;
        cp_async16((uint32_t)__cvta_generic_to_shared(&As[buf][ar0][ac0]),
                   A + (size_t)(bm + ar0) * K + k0 + ac0);
        cp_async16((uint32_t)__cvta_generic_to_shared(&As[buf][ar0 + 64][ac0]),
                   A + (size_t)(bm + ar0 + 64) * K + k0 + ac0);
        cp_async16((uint32_t)__cvta_generic_to_shared(&Bs[buf][bk0][bn0]),
                   W + (size_t)(k0 + bk0) * N + bn + bn0);
        cp_async16((uint32_t)__cvta_generic_to_shared(&Bs[buf][bk0 + 8][bn0]),
                   W + (size_t)(k0 + bk0 + 8) * N + bn + bn0);
    };

    issue_tile(0, 0);
    CP_COMMIT();

    for (int kt = 0; kt < KT; kt++) {
        if (kt + 1 < KT) issue_tile(kt + 1, (kt + 1) & 1);
        CP_COMMIT();
        CP_WAIT1();
        __syncthreads();

        const int buf = kt & 1;
        #pragma unroll
        for (int ks = 0; ks < 2; ks++) {
            const int kb = ks * 8;
            uint32_t afr[4][4], bfr[4][2];
            #pragma unroll
            for (int mf = 0; mf < 4; mf++) {
                const int mb = wm * 64 + mf * 16;
                afr[mf][0] = __float_as_uint(As[buf][mb + gid    ][kb + tig    ]);
                afr[mf][1] = __float_as_uint(As[buf][mb + gid + 8][kb + tig    ]);
                afr[mf][2] = __float_as_uint(As[buf][mb + gid    ][kb + tig + 4]);
                afr[mf][3] = __float_as_uint(As[buf][mb + gid + 8][kb + tig + 4]);
            }
            #pragma unroll
            for (int nf = 0; nf < 4; nf++) {
                const int nb = wn * 32 + nf * 8;
                bfr[nf][0] = __float_as_uint(Bs[buf][kb + tig    ][nb + gid]);
                bfr[nf][1] = __float_as_uint(Bs[buf][kb + tig + 4][nb + gid]);
            }
            #pragma unroll
            for (int mf = 0; mf < 4; mf++)
                #pragma unroll
                for (int nf = 0; nf < 4; nf++)
                    mma_tf32(c[mf][nf],
                             afr[mf][0], afr[mf][1], afr[mf][2], afr[mf][3],
                             bfr[nf][0], bfr[nf][1]);
        }
        __syncthreads();
    }

    #pragma unroll
    for (int mf = 0; mf < 4; mf++) {
        const int r0 = bm + wm * 64 + mf * 16 + gid;
        #pragma unroll
        for (int nf = 0; nf < 4; nf++) {
            const int col = bn + wn * 32 + nf * 8 + 2 * tig;
            const float bx = bias[col], by = bias[col + 1];
            float2 v0, v1;
            v0.x = c[mf][nf][0] + bx; v0.y = c[mf][nf][1] + by;
            v1.x = c[mf][nf][2] + bx; v1.y = c[mf][nf][3] + by;
            if (RELU) {
                v0.x = fmaxf(v0.x, 0.f); v0.y = fmaxf(v0.y, 0.f);
                v1.x = fmaxf(v1.x, 0.f); v1.y = fmaxf(v1.y, 0.f);
            }
            *(float2*)&C[(size_t)r0       * N + col] = v0;
            *(float2*)&C[(size_t)(r0 + 8) * N + col] = v1;
        }
    }
}

// ---------------------------------------------------------------------------
// Deformable sampling v2: one warp per (token, head).
// 4 point-groups x 8 lanes; lane carries float4 (4 channels).
// Group g handles point p=g of each level. Branch-free clamp+mask gathers
// (LDG.128), cross-group shfl reduction, single 128B store by lanes 0-7.
// ---------------------------------------------------------------------------
__global__ void __launch_bounds__(256)
sample_kernel(const float* __restrict__ refpts)
{
    const int warp = (blockIdx.x * blockDim.x + threadIdx.x) >> 5;
    const int lane = threadIdx.x & 31;
    if (warp >= BS_TOK * NH) return;
    const int h = warp & (NH - 1);
    const int t = warp >> 3;                 // global token (b*S + q)
    const int b = t / S_TOK;
    const int base = b * S_TOK;

    const int grp = lane >> 3;               // 0..3 point group
    const int cl  = (lane & 7) * 4;          // channel offset within head

    // softmax over 16 logits (redundant per lane; L1-broadcast loads)
    const float* lg = g_attn + (size_t)t * 128 + h * 16;
    float w[16];
    float mx = -1e30f;
    #pragma unroll
    for (int i = 0; i < 16; i++) { w[i] = lg[i]; mx = fmaxf(mx, w[i]); }
    float ssum = 0.f;
    #pragma unroll
    for (int i = 0; i < 16; i++) { w[i] = __expf(w[i] - mx); ssum += w[i]; }
    const float inv = 1.f / ssum;

    const float* offp = g_off + (size_t)t * 256 + h * 32; // (NL,NP,2)
    const float* rp   = refpts + (size_t)t * NL * 2;      // (NL,2)
    const float* vch  = g_value + h * 32 + cl;            // channel base

    float4 acc = make_float4(0.f, 0.f, 0.f, 0.f);

    #pragma unroll
    for (int l = 0; l < NL; l++) {
        const int W = c_lvlW[l];
        const int H = W;
        const int lstart = c_lvlStart[l];
        const float rx = rp[l * 2 + 0];
        const float ry = rp[l * 2 + 1];
        const int p = grp;                   // this group's point

        const float ox = offp[l * 8 + p * 2 + 0];
        const float oy = offp[l * 8 + p * 2 + 1];
        // mirror reference rounding: loc = ref + off/norm; x = loc*W - 0.5
        const float locx = rx + ox / (float)W;
        const float locy = ry + oy / (float)H;
        const float x = locx * (float)W - 0.5f;
        const float y = locy * (float)H - 0.5f;
        const float x0f = floorf(x), y0f = floorf(y);
        const float wx = x - x0f, wy = y - y0f;
        const int x0 = (int)x0f, y0 = (int)y0f;
        const int x1 = x0 + 1,   y1 = y0 + 1;
        const float aw = w[l * 4 + p] * inv;

        // validity masks (reference semantics)
        const float vx0 = (x0 >= 0 && x0 < W) ? 1.f : 0.f;
        const float vx1 = (x1 >= 0 && x1 < W) ? 1.f : 0.f;
        const float vy0 = (y0 >= 0 && y0 < H) ? 1.f : 0.f;
        const float vy1 = (y1 >= 0 && y1 < H) ? 1.f : 0.f;

        // clamped (always in-bounds) row indices
        const int x0c = min(max(x0, 0), W - 1);
        const int x1c = min(max(x1, 0), W - 1);
        const int y0c = min(max(y0, 0), H - 1);
        const int y1c = min(max(y1, 0), H - 1);
        const int r00 = base + lstart + y0c * W + x0c;
        const int r01 = base + lstart + y0c * W + x1c;
        const int r10 = base + lstart + y1c * W + x0c;
        const int r11 = base + lstart + y1c * W + x1c;

        // unconditional wide gathers
        const float4 v00 = *(const float4*)(vch + (size_t)r00 * 256);
        const float4 v01 = *(const float4*)(vch + (size_t)r01 * 256);
        const float4 v10 = *(const float4*)(vch + (size_t)r10 * 256);
        const float4 v11 = *(const float4*)(vch + (size_t)r11 * 256);

        const float w00 = aw * ((1.f - wx) * (1.f - wy)) * (vx0 * vy0);
        const float w01 = aw * (wx * (1.f - wy))         * (vx1 * vy0);
        const float w10 = aw * ((1.f - wx) * wy)         * (vx0 * vy1);
        const float w11 = aw * (wx * wy)                 * (vx1 * vy1);

        acc.x += w00 * v00.x + w01 * v01.x + w10 * v10.x + w11 * v11.x;
        acc.y += w00 * v00.y + w01 * v01.y + w10 * v10.y + w11 * v11.y;
        acc.z += w00 * v00.z + w01 * v01.z + w10 * v10.z + w11 * v11.z;
        acc.w += w00 * v00.w + w01 * v01.w + w10 * v10.w + w11 * v11.w;
    }

    // reduce across the 4 point groups (lanes differing in bits 3,4)
    #pragma unroll
    for (int o = 8; o <= 16; o <<= 1) {
        acc.x += __shfl_xor_sync(0xffffffffu, acc.x, o);
        acc.y += __shfl_xor_sync(0xffffffffu, acc.y, o);
        acc.z += __shfl_xor_sync(0xffffffffu, acc.z, o);
        acc.w += __shfl_xor_sync(0xffffffffu, acc.w, o);
    }
    if (grp == 0)
        *(float4*)&g_acc[(size_t)t * 256 + h * 32 + cl] = acc;
}

// ---------------------------------------------------------------------------
// out = LayerNorm(a + b) * g + beta, over D=256 per token. 1 block / token.
// ---------------------------------------------------------------------------
__global__ void __launch_bounds__(256)
add_ln_kernel(const float* __restrict__ a, const float* __restrict__ b,
              const float* __restrict__ g, const float* __restrict__ be,
              float* __restrict__ out)
{
    const int t = blockIdx.x;
    const int i = threadIdx.x;
    const size_t idx = (size_t)t * DMODEL + i;
    const float v = a[idx] + b[idx];

    float s = v, s2 = v * v;
    #pragma unroll
    for (int o = 16; o > 0; o >>= 1) {
        s  += __shfl_xor_sync(0xffffffffu, s,  o);
        s2 += __shfl_xor_sync(0xffffffffu, s2, o);
    }
    __shared__ float sh[8], sh2[8];
    const int wid = i >> 5, lane = i & 31;
    if (lane == 0) { sh[wid] = s; sh2[wid] = s2; }
    __syncthreads();
    float ts = 0.f, ts2 = 0.f;
    #pragma unroll
    for (int k = 0; k < 8; k++) { ts += sh[k]; ts2 += sh2[k]; }

    const float mean = ts * (1.f / DMODEL);
    const float var  = ts2 * (1.f / DMODEL) - mean * mean;
    const float rstd = rsqrtf(var + 1e-5f);
    out[idx] = (v - mean) * rstd * g[i] + be[i];
}

// ---------------------------------------------------------------------------
// Launch
// ---------------------------------------------------------------------------
extern "C" void kernel_launch(void* const* d_in, const int* in_sizes, int n_in,
                              void* d_out, int out_size)
{
    const float* src    = (const float*)d_in[0];
    const float* pos    = (const float*)d_in[1];
    const float* refpts = (const float*)d_in[2];
    // d_in[3] spatial_shapes, d_in[4] level_start_index: compile-time constants
    const float* W_off  = (const float*)d_in[5];
    const float* b_off  = (const float*)d_in[6];
    const float* W_attn = (const float*)d_in[7];
    const float* b_attn = (const float*)d_in[8];
    const float* W_val  = (const float*)d_in[9];
    const float* b_val  = (const float*)d_in[10];
    const float* W_out  = (const float*)d_in[11];
    const float* b_out  = (const float*)d_in[12];
    const float* W_ffn1 = (const float*)d_in[13];
    const float* b_ffn1 = (const float*)d_in[14];
    const float* W_ffn2 = (const float*)d_in[15];
    const float* b_ffn2 = (const float*)d_in[16];
    const float* ln1_g  = (const float*)d_in[17];
    const float* ln1_b  = (const float*)d_in[18];
    const float* ln2_g  = (const float*)d_in[19];
    const float* ln2_b  = (const float*)d_in[20];
    float* out = (float*)d_out;

    float *q, *value, *off, *attn, *acc, *h;
    cudaGetSymbolAddress((void**)&q,     g_q);
    cudaGetSymbolAddress((void**)&value, g_value);
    cudaGetSymbolAddress((void**)&off,   g_off);
    cudaGetSymbolAddress((void**)&attn,  g_attn);
    cudaGetSymbolAddress((void**)&acc,   g_acc);
    cudaGetSymbolAddress((void**)&h,     g_h);

    // buffer aliasing (lifetimes don't overlap):
    float* src2 = q;      // q dead after step 4; src2 live steps 6-7
    float* x    = value;  // value dead after step 5; x live steps 7-10
    float* ffn  = acc;    // acc dead after step 6; ffn live steps 9-10

    const int MB = BS_TOK / 128;   // 340 row-tiles

    // 1) q = src + pos
    {
        int n4 = BS_TOK * DMODEL / 4;
        add_kernel<<<(n4 + 255) / 256, 256>>>(src, pos, q, n4);
    }
    // 2) value = src @ W_val + b_val
    gemm_tf32<false><<<dim3(MB, DMODEL / 128), 256>>>(src, W_val, b_val, value,
                                                      BS_TOK, DMODEL, DMODEL);
    // 3) off = q @ W_off + b_off
    gemm_tf32<false><<<dim3(MB, 256 / 128), 256>>>(q, W_off, b_off, off,
                                                   BS_TOK, 256, DMODEL);
    // 4) attn logits = q @ W_attn + b_attn
    gemm_tf32<false><<<dim3(MB, 1), 256>>>(q, W_attn, b_attn, attn,
                                           BS_TOK, 128, DMODEL);
    // 5) deformable sampling -> acc
    {
        int warps = BS_TOK * NH;                  // 348160
        int blocks = warps / 8;                   // 256 thr = 8 warps
        sample_kernel<<<blocks, 256>>>(refpts);
    }
    // 6) src2 = acc @ W_out + b_out   (src2 aliases q)
    gemm_tf32<false><<<dim3(MB, DMODEL / 128), 256>>>(acc, W_out, b_out, src2,
                                                      BS_TOK, DMODEL, DMODEL);
    // 7) x = LN(src + src2)           (x aliases value)
    add_ln_kernel<<<BS_TOK, 256>>>(src, src2, ln1_g, ln1_b, x);
    // 8) h = relu(x @ W_ffn1 + b_ffn1)
    gemm_tf32<true><<<dim3(MB, DFF / 128), 256>>>(x, W_ffn1, b_ffn1, h,
                                                  BS_TOK, DFF, DMODEL);
    // 9) ffn = h @ W_ffn2 + b_ffn2    (ffn aliases acc)
    gemm_tf32<false><<<dim3(MB, DMODEL / 128), 256>>>(h, W_ffn2, b_ffn2, ffn,
                                                      BS_TOK, DMODEL, DFF);
    // 10) out = LN(x + ffn)
    add_ln_kernel<<<BS_TOK, 256>>>(x, ffn, ln2_g, ln2_b, out);
}